// round 16
// baseline (speedup 1.0000x reference)
#include <cuda_runtime.h>
#include <cuda_bf16.h>
#include <cuda_fp16.h>
#include <cstdint>

#define DIM 1024
#define S_LEN 4096
#define NH 16
#define HD 64

// Scratch (allocation-free rule: __device__ globals)
__device__ __half g_x [S_LEN * DIM];
__device__ __half g_wq[DIM * DIM];
__device__ __half g_wk[DIM * DIM];
__device__ __half g_wv[DIM * DIM];
__device__ __half g_wo[DIM * DIM];
__device__ __half g_Q [S_LEN * DIM];
__device__ __half g_K [S_LEN * DIM];
__device__ __half g_V [S_LEN * DIM];
__device__ __half g_Z [S_LEN * DIM];

#define QSCALE 0.18033688f   // 0.125 * log2(e): logits in log2 domain

// ===========================================================================
// Base-ISA tensor-core helpers (compute_103-safe: ldmatrix + mma.sync)
// ===========================================================================
__device__ __forceinline__ uint32_t smem_u32(const void* p) {
    uint32_t a;
    asm("{ .reg .u64 t; cvta.to.shared.u64 t, %1; cvt.u32.u64 %0, t; }"
        : "=r"(a) : "l"(p));
    return a;
}

__device__ __forceinline__ void ldm_x4(uint32_t* f, uint32_t addr) {
    asm volatile("ldmatrix.sync.aligned.m8n8.x4.shared.b16 {%0,%1,%2,%3}, [%4];"
                 : "=r"(f[0]), "=r"(f[1]), "=r"(f[2]), "=r"(f[3]) : "r"(addr));
}
__device__ __forceinline__ void ldm_x4t(uint32_t* f, uint32_t addr) {
    asm volatile("ldmatrix.sync.aligned.m8n8.x4.trans.shared.b16 {%0,%1,%2,%3}, [%4];"
                 : "=r"(f[0]), "=r"(f[1]), "=r"(f[2]), "=r"(f[3]) : "r"(addr));
}
__device__ __forceinline__ void mma_f16(float* c, const uint32_t* a,
                                        const uint32_t* b) {
    asm volatile(
        "mma.sync.aligned.m16n8k16.row.col.f32.f16.f16.f32 "
        "{%0,%1,%2,%3}, {%4,%5,%6,%7}, {%8,%9}, {%0,%1,%2,%3};"
        : "+f"(c[0]), "+f"(c[1]), "+f"(c[2]), "+f"(c[3])
        : "r"(a[0]), "r"(a[1]), "r"(a[2]), "r"(a[3]), "r"(b[0]), "r"(b[1]));
}

__device__ __forceinline__ uint32_t pack_h2(float x, float y) {
    __half2 p;
    p.x = __float2half_rn(x);
    p.y = __float2half_rn(y);
    return *(uint32_t*)&p;
}

#define CP_ASYNC16(dst, src)                                                   \
    asm volatile("cp.async.cg.shared.global [%0], [%1], 16;"                   \
                 :: "r"(dst), "l"(src))
#define CP_COMMIT() asm volatile("cp.async.commit_group;" ::: "memory")
#define CP_WAIT0()  asm volatile("cp.async.wait_group 0;" ::: "memory")

// ===========================================================================
// One-time fp32 -> fp16 conversions
// ===========================================================================
__global__ __launch_bounds__(256)
void cvt_x(const float* __restrict__ src, __half* __restrict__ dst) {
    int i = (blockIdx.x * 256 + threadIdx.x) * 4;
    float4 v = *(const float4*)(src + i);
    *(uint2*)(dst + i) = make_uint2(pack_h2(v.x, v.y), pack_h2(v.z, v.w));
}

// all four weight matrices in one launch (blockIdx.y selects)
__global__ __launch_bounds__(256)
void cvt_w(const float* __restrict__ wq, const float* __restrict__ wk,
           const float* __restrict__ wv, const float* __restrict__ wo,
           __half* __restrict__ dq, __half* __restrict__ dk,
           __half* __restrict__ dv, __half* __restrict__ dwo) {
    int z = blockIdx.y;
    const float* src = (z == 0) ? wq : (z == 1) ? wk : (z == 2) ? wv : wo;
    __half* dst = (z == 0) ? dq : (z == 1) ? dk : (z == 2) ? dv : dwo;
    int i = (blockIdx.x * 256 + threadIdx.x) * 4;
    float4 v = *(const float4*)(src + i);
    *(uint2*)(dst + i) = make_uint2(pack_h2(v.x, v.y), pack_h2(v.z, v.w));
}

// ===========================================================================
// All-fp16 1-pass cp.async-pipelined GEMM-NT:  C = A * B^T
// 128x128 CTA tile, BK=32, 256 threads (8 warps 2x4), warp tile 64x32.
// MODE 1: out single fp16 (scaled)   (Q, K, V projections)
// MODE 2: out fp32                   (output projection)
// ===========================================================================
#define RS 40
#define SEG (128 * RS)
#define STAGE_ELEMS (2 * SEG)             // A | B
#define STAGE_BYTES (STAGE_ELEMS * 2)     // 20480
#define GEMM_SMEM (2 * STAGE_BYTES)       // 40960

template <int MODE>
__device__ __forceinline__
void gemm_body(const __half* __restrict__ Ax, const __half* __restrict__ Bw,
               float* __restrict__ C, __half* __restrict__ Ch,
               float scale, int M, int N, int Kd, __half* smem) {
    const uint32_t sb = smem_u32(smem);
    const int t    = threadIdx.x;
    const int lane = t & 31;
    const int wid  = t >> 5;
    const int wm   = (wid >> 2) * 64;
    const int wn   = (wid & 3) * 32;
    const int bm   = blockIdx.y * 128;
    const int bn   = blockIdx.x * 128;

    auto issue = [&](int c, int stage) {
        const int k0 = c * 32;
        uint32_t dbase = sb + stage * STAGE_BYTES;
#pragma unroll
        for (int i = 0; i < 4; i++) {
            int idx = t + i * 256;        // 0..1023
            int mtx = idx >> 9;           // 0=A 1=B
            int r   = (idx >> 2) & 127;
            int c16 = (idx & 3) * 8;
            const __half* src =
                (mtx == 0) ? Ax + (size_t)(bm + r) * Kd + k0 + c16
                           : Bw + (size_t)(bn + r) * Kd + k0 + c16;
            uint32_t dst = dbase + ((mtx * 128 + r) * RS + c16) * 2;
            CP_ASYNC16(dst, src);
        }
        CP_COMMIT();
    };

    float acc[4][4][4] = {};

    const int nchunks = Kd / 32;
    issue(0, 0);

    for (int c = 0; c < nchunks; c++) {
        const int stage = c & 1;
        CP_WAIT0();
        __syncthreads();
        if (c + 1 < nchunks) issue(c + 1, stage ^ 1);

        const uint32_t sstage = sb + stage * STAGE_BYTES;
        const uint32_t a_base =
            sstage + ((wm + (lane & 15)) * RS + (lane >> 4) * 8) * 2;
        const uint32_t b_base =
            sstage + SEG * 2 +
            ((wn + (lane & 15)) * RS + (lane >> 4) * 8) * 2;

#pragma unroll
        for (int ks = 0; ks < 2; ks++) {
            uint32_t ah[4][4];
#pragma unroll
            for (int mt = 0; mt < 4; mt++)
                ldm_x4(ah[mt], a_base + (mt * 16 * RS + ks * 16) * 2);
#pragma unroll
            for (int ntp = 0; ntp < 2; ntp++) {
                uint32_t fb[4];
                ldm_x4(fb, b_base + (ntp * 16 * RS + ks * 16) * 2);
                uint32_t be[2] = {fb[0], fb[2]};
                uint32_t bo[2] = {fb[1], fb[3]};
#pragma unroll
                for (int mt = 0; mt < 4; mt++) {
                    mma_f16(acc[mt][2 * ntp],     ah[mt], be);
                    mma_f16(acc[mt][2 * ntp + 1], ah[mt], bo);
                }
            }
        }
        __syncthreads();
    }

    const int r0 = bm + wm + (lane >> 2);
    const int c0 = bn + wn + (lane & 3) * 2;
#pragma unroll
    for (int mt = 0; mt < 4; mt++)
#pragma unroll
        for (int nt = 0; nt < 4; nt++) {
            size_t o0 = (size_t)(r0 + mt * 16) * N + c0 + nt * 8;
            size_t o1 = o0 + (size_t)8 * N;
            if (MODE == 2) {
                *(float2*)(C + o0) = make_float2(acc[mt][nt][0], acc[mt][nt][1]);
                *(float2*)(C + o1) = make_float2(acc[mt][nt][2], acc[mt][nt][3]);
            } else {
                *(uint32_t*)(Ch + o0) = pack_h2(acc[mt][nt][0] * scale,
                                                acc[mt][nt][1] * scale);
                *(uint32_t*)(Ch + o1) = pack_h2(acc[mt][nt][2] * scale,
                                                acc[mt][nt][3] * scale);
            }
        }
}

__global__ __launch_bounds__(256, 1)
void gemm_h(const __half* __restrict__ Ax, const __half* __restrict__ Bw,
            __half* __restrict__ Ch, float scale) {
    extern __shared__ __half smem[];
    gemm_body<1>(Ax, Bw, nullptr, Ch, scale, S_LEN, DIM, DIM, smem);
}
__global__ __launch_bounds__(256, 1)
void gemm_out(const __half* __restrict__ Ax, const __half* __restrict__ Bw,
              float* __restrict__ C) {
    extern __shared__ __half smem[];
    gemm_body<2>(Ax, Bw, C, nullptr, 1.0f, S_LEN, DIM, DIM, smem);
}

// ===========================================================================
// Tensor-core causal flash attention, all 1-pass fp16 mma.
// QK: Q (register-resident) x K.  PV: P single x V single.
// CTA = 128 q rows x 1 head; 512 threads = 8 row-groups x 2 key-halves.
// ===========================================================================
#define RS2 72
#define ATTN_SMEM (384 * RS2 * 2)   // 55296 bytes
#define MRG_STRIDE 68
#define MRG_GRP (16 * MRG_STRIDE + 32)

__global__ __launch_bounds__(512, 1)
void attn_mma(const __half* __restrict__ Q, const __half* __restrict__ K,
              const __half* __restrict__ V, __half* __restrict__ Z) {
    extern __shared__ __half sm[];
    const uint32_t sb = smem_u32(sm);
    const int qb   = (int)gridDim.x - 1 - (int)blockIdx.x;  // big tiles first
    const int h    = blockIdx.y;
    const int t    = threadIdx.x;
    const int lane = t & 31;
    const int w    = t >> 5;
    const int g    = w >> 1;      // row group 0..7
    const int hf   = w & 1;       // key half 0/1

    auto issue_kv = [&](int kb, int s) {
#pragma unroll
        for (int i = 0; i < 2; i++) {
            int idx = t + i * 512;
            int mtx = idx >> 9;           // 0=K 1=V
            int r   = (idx >> 3) & 63;
            int c8  = (idx & 7) * 8;
            const __half* src =
                (mtx ? V : K) + (size_t)(kb * 64 + r) * DIM + h * 64 + c8;
            uint32_t dst =
                sb + ((128 + s * 128 + mtx * 64 + r) * RS2 + c8) * 2;
            CP_ASYNC16(dst, src);
        }
    };

    // ---- prologue: Q + stage 0 K/V ----
    {
#pragma unroll
        for (int i = 0; i < 2; i++) {
            int idx = t + i * 512;
            int r   = (idx >> 3) & 127;
            int c8  = (idx & 7) * 8;
            const __half* src =
                Q + (size_t)(qb * 128 + r) * DIM + h * 64 + c8;
            uint32_t dst = sb + (r * RS2 + c8) * 2;
            CP_ASYNC16(dst, src);
        }
        issue_kv(0, 0);
        CP_COMMIT();
        CP_WAIT0();
    }
    __syncthreads();

    // ---- Q fragments: register-resident for the whole kb loop ----
    uint32_t qf[4][4];
    {
        const uint32_t q_base =
            sb + ((g * 16 + (lane & 15)) * RS2 + (lane >> 4) * 8) * 2;
#pragma unroll
        for (int ks = 0; ks < 4; ks++)
            ldm_x4(qf[ks], q_base + ks * 32);
    }

    float o[8][4] = {};
    float m0 = -1e30f, m1 = -1e30f, l0 = 0.f, l1 = 0.f;
    const int row0 = qb * 128 + g * 16 + (lane >> 2);

    const int nkb = 2 * qb + 2;
    for (int kb = 0; kb < nkb; kb++) {
        const int s = kb & 1;
        if (kb + 1 < nkb) { issue_kv(kb + 1, s ^ 1); CP_COMMIT(); }

        const bool active = (kb * 64 + hf * 32 <= qb * 128 + g * 16 + 15);
        if (active) {
            const int KB = 128 + s * 128;        // K rows
            const int VB = KB + 64;              // V rows

            // ---- S = Q K^T on this warp's 32 keys (fp16 1-pass) ----
            float c[4][4] = {};
#pragma unroll
            for (int ks = 0; ks < 4; ks++) {
#pragma unroll
                for (int ntp = 0; ntp < 2; ntp++) {
                    uint32_t fh[4];
                    uint32_t addr = sb +
                        ((KB + hf * 32 + ntp * 16 + (lane & 15)) * RS2 +
                         ks * 16 + (lane >> 4) * 8) * 2;
                    ldm_x4(fh, addr);
                    uint32_t beh[2] = {fh[0], fh[2]};
                    uint32_t boh[2] = {fh[1], fh[3]};
                    mma_f16(c[2 * ntp],     qf[ks], beh);
                    mma_f16(c[2 * ntp + 1], qf[ks], boh);
                }
            }

            // ---- causal mask ----
            if (kb * 64 + hf * 32 + 31 > row0) {
                const int colbase = kb * 64 + hf * 32 + (lane & 3) * 2;
#pragma unroll
                for (int nt = 0; nt < 4; nt++) {
                    int cc = colbase + nt * 8;
                    if (cc     > row0)     c[nt][0] = -1e30f;
                    if (cc + 1 > row0)     c[nt][1] = -1e30f;
                    if (cc     > row0 + 8) c[nt][2] = -1e30f;
                    if (cc + 1 > row0 + 8) c[nt][3] = -1e30f;
                }
            }

            // ---- online softmax (log2 domain) ----
            float mx0 = -1e30f, mx1 = -1e30f;
#pragma unroll
            for (int nt = 0; nt < 4; nt++) {
                mx0 = fmaxf(mx0, fmaxf(c[nt][0], c[nt][1]));
                mx1 = fmaxf(mx1, fmaxf(c[nt][2], c[nt][3]));
            }
            mx0 = fmaxf(mx0, __shfl_xor_sync(0xffffffffu, mx0, 1));
            mx0 = fmaxf(mx0, __shfl_xor_sync(0xffffffffu, mx0, 2));
            mx1 = fmaxf(mx1, __shfl_xor_sync(0xffffffffu, mx1, 1));
            mx1 = fmaxf(mx1, __shfl_xor_sync(0xffffffffu, mx1, 2));
            float M0 = fmaxf(m0, mx0);
            float M1 = fmaxf(m1, mx1);
            float sc0 = exp2f(m0 - M0);
            float sc1 = exp2f(m1 - M1);
            m0 = M0; m1 = M1;
            float s0 = 0.f, s1 = 0.f;
#pragma unroll
            for (int nt = 0; nt < 4; nt++) {
                c[nt][0] = exp2f(c[nt][0] - M0);
                c[nt][1] = exp2f(c[nt][1] - M0);
                c[nt][2] = exp2f(c[nt][2] - M1);
                c[nt][3] = exp2f(c[nt][3] - M1);
                s0 += c[nt][0] + c[nt][1];
                s1 += c[nt][2] + c[nt][3];
            }
            s0 += __shfl_xor_sync(0xffffffffu, s0, 1);
            s0 += __shfl_xor_sync(0xffffffffu, s0, 2);
            s1 += __shfl_xor_sync(0xffffffffu, s1, 1);
            s1 += __shfl_xor_sync(0xffffffffu, s1, 2);
            l0 = l0 * sc0 + s0;
            l1 = l1 * sc1 + s1;
#pragma unroll
            for (int nt = 0; nt < 8; nt++) {
                o[nt][0] *= sc0; o[nt][1] *= sc0;
                o[nt][2] *= sc1; o[nt][3] *= sc1;
            }

            // ---- O += P V (fp16 1-pass: P single x V single) ----
#pragma unroll
            for (int ks = 0; ks < 2; ks++) {
                uint32_t ph[4];
                ph[0] = pack_h2(c[2 * ks][0],     c[2 * ks][1]);
                ph[1] = pack_h2(c[2 * ks][2],     c[2 * ks][3]);
                ph[2] = pack_h2(c[2 * ks + 1][0], c[2 * ks + 1][1]);
                ph[3] = pack_h2(c[2 * ks + 1][2], c[2 * ks + 1][3]);
#pragma unroll
                for (int ntp = 0; ntp < 4; ntp++) {
                    uint32_t fh[4];
                    uint32_t addr = sb +
                        ((VB + hf * 32 + ks * 16 + (lane & 15)) * RS2 +
                         ntp * 16 + (lane >> 4) * 8) * 2;
                    ldm_x4t(fh, addr);
                    uint32_t veh[2] = {fh[0], fh[1]};
                    uint32_t voh[2] = {fh[2], fh[3]};
                    mma_f16(o[2 * ntp],     ph, veh);
                    mma_f16(o[2 * ntp + 1], ph, voh);
                }
            }
        }
        if (kb + 1 < nkb) CP_WAIT0();
        __syncthreads();
    }

    // ---- merge warp pairs via smem (hf=1 publishes, hf=0 merges+stores) ----
    float* smf = (float*)sm;
    const int r4 = lane >> 2;
    const int c2 = (lane & 3) * 2;
    if (hf == 1) {
        float* gbuf = smf + g * MRG_GRP;
#pragma unroll
        for (int nt = 0; nt < 8; nt++) {
            float* p0 = gbuf + r4 * MRG_STRIDE + c2 + nt * 8;
            p0[0] = o[nt][0];
            p0[1] = o[nt][1];
            float* p1 = gbuf + (r4 + 8) * MRG_STRIDE + c2 + nt * 8;
            p1[0] = o[nt][2];
            p1[1] = o[nt][3];
        }
        if ((lane & 3) == 0) {
            gbuf[16 * MRG_STRIDE + r4]      = m0;
            gbuf[16 * MRG_STRIDE + 8 + r4]  = m1;
            gbuf[16 * MRG_STRIDE + 16 + r4] = l0;
            gbuf[16 * MRG_STRIDE + 24 + r4] = l1;
        }
    }
    __syncthreads();
    if (hf == 0) {
        float* gbuf = smf + g * MRG_GRP;
        float mb0 = gbuf[16 * MRG_STRIDE + r4];
        float mb1 = gbuf[16 * MRG_STRIDE + 8 + r4];
        float lb0 = gbuf[16 * MRG_STRIDE + 16 + r4];
        float lb1 = gbuf[16 * MRG_STRIDE + 24 + r4];
        float M0 = fmaxf(m0, mb0);
        float M1 = fmaxf(m1, mb1);
        float ea0 = exp2f(m0 - M0), eb0 = exp2f(mb0 - M0);
        float ea1 = exp2f(m1 - M1), eb1 = exp2f(mb1 - M1);
        float inv0 = 1.0f / (l0 * ea0 + lb0 * eb0);
        float inv1 = 1.0f / (l1 * ea1 + lb1 * eb1);
        size_t zoff0 = (size_t)row0 * DIM + h * HD + c2;
        size_t zoff1 = zoff0 + (size_t)8 * DIM;
#pragma unroll
        for (int nt = 0; nt < 8; nt++) {
            float* p0 = gbuf + r4 * MRG_STRIDE + c2 + nt * 8;
            float* p1 = gbuf + (r4 + 8) * MRG_STRIDE + c2 + nt * 8;
            float a0 = (o[nt][0] * ea0 + p0[0] * eb0) * inv0;
            float a1 = (o[nt][1] * ea0 + p0[1] * eb0) * inv0;
            float b0 = (o[nt][2] * ea1 + p1[0] * eb1) * inv1;
            float b1 = (o[nt][3] * ea1 + p1[1] * eb1) * inv1;
            *(uint32_t*)(Z + zoff0 + nt * 8) = pack_h2(a0, a1);
            *(uint32_t*)(Z + zoff1 + nt * 8) = pack_h2(b0, b1);
        }
    }
}

// ===========================================================================
extern "C" void kernel_launch(void* const* d_in, const int* in_sizes, int n_in,
                              void* d_out, int out_size) {
    const float* x  = (const float*)d_in[0];
    const float* Wq = (const float*)d_in[1];
    const float* Wk = (const float*)d_in[2];
    const float* Wv = (const float*)d_in[3];
    const float* Wo = (const float*)d_in[4];
    float* out = (float*)d_out;

    __half *dx, *dwq, *dwk, *dwv, *dwo, *dQ, *dK, *dV, *dZ;
    cudaGetSymbolAddress((void**)&dx, g_x);
    cudaGetSymbolAddress((void**)&dwq, g_wq);
    cudaGetSymbolAddress((void**)&dwk, g_wk);
    cudaGetSymbolAddress((void**)&dwv, g_wv);
    cudaGetSymbolAddress((void**)&dwo, g_wo);
    cudaGetSymbolAddress((void**)&dQ, g_Q);
    cudaGetSymbolAddress((void**)&dK, g_K);
    cudaGetSymbolAddress((void**)&dV, g_V);
    cudaGetSymbolAddress((void**)&dZ, g_Z);

    cudaFuncSetAttribute(gemm_h,
                         cudaFuncAttributeMaxDynamicSharedMemorySize, GEMM_SMEM);
    cudaFuncSetAttribute(gemm_out,
                         cudaFuncAttributeMaxDynamicSharedMemorySize, GEMM_SMEM);
    cudaFuncSetAttribute(attn_mma,
                         cudaFuncAttributeMaxDynamicSharedMemorySize, ATTN_SMEM);

    // one-time fp16 conversions
    cvt_x<<<(S_LEN * DIM) / 1024, 256>>>(x, dx);
    cvt_w<<<dim3((DIM * DIM) / 1024, 4), 256>>>(Wq, Wk, Wv, Wo,
                                                dwq, dwk, dwv, dwo);

    dim3 gproj(DIM / 128, S_LEN / 128);   // (8, 32)
    gemm_h<<<gproj, 256, GEMM_SMEM>>>(dx, dwq, dQ, QSCALE);
    gemm_h<<<gproj, 256, GEMM_SMEM>>>(dx, dwk, dK, 1.0f);
    gemm_h<<<gproj, 256, GEMM_SMEM>>>(dx, dwv, dV, 1.0f);

    attn_mma<<<dim3(S_LEN / 128, NH), 512, ATTN_SMEM>>>(dQ, dK, dV, dZ);

    gemm_out<<<gproj, 256, GEMM_SMEM>>>(dZ, dwo, out);
}

// round 17
// speedup vs baseline: 1.5352x; 1.5352x over previous
#include <cuda_runtime.h>
#include <cuda_bf16.h>
#include <cuda_fp16.h>
#include <cstdint>

#define DIM 1024
#define S_LEN 4096
#define NH 16
#define HD 64

// Scratch (allocation-free rule: __device__ globals)
__device__ __half g_x [S_LEN * DIM];
__device__ __half g_wq[DIM * DIM];
__device__ __half g_wk[DIM * DIM];
__device__ __half g_wv[DIM * DIM];
__device__ __half g_wo[DIM * DIM];
__device__ __half g_Q [S_LEN * DIM];
__device__ __half g_K [S_LEN * DIM];
__device__ __half g_V [S_LEN * DIM];
__device__ __half g_Z [S_LEN * DIM];

#define QSCALE 0.18033688f   // 0.125 * log2(e): logits in log2 domain

// ===========================================================================
// Base-ISA tensor-core helpers (compute_103-safe: ldmatrix + mma.sync)
// ===========================================================================
__device__ __forceinline__ uint32_t smem_u32(const void* p) {
    uint32_t a;
    asm("{ .reg .u64 t; cvta.to.shared.u64 t, %1; cvt.u32.u64 %0, t; }"
        : "=r"(a) : "l"(p));
    return a;
}

__device__ __forceinline__ void ldm_x4(uint32_t* f, uint32_t addr) {
    asm volatile("ldmatrix.sync.aligned.m8n8.x4.shared.b16 {%0,%1,%2,%3}, [%4];"
                 : "=r"(f[0]), "=r"(f[1]), "=r"(f[2]), "=r"(f[3]) : "r"(addr));
}
__device__ __forceinline__ void ldm_x4t(uint32_t* f, uint32_t addr) {
    asm volatile("ldmatrix.sync.aligned.m8n8.x4.trans.shared.b16 {%0,%1,%2,%3}, [%4];"
                 : "=r"(f[0]), "=r"(f[1]), "=r"(f[2]), "=r"(f[3]) : "r"(addr));
}
__device__ __forceinline__ void mma_f16(float* c, const uint32_t* a,
                                        const uint32_t* b) {
    asm volatile(
        "mma.sync.aligned.m16n8k16.row.col.f32.f16.f16.f32 "
        "{%0,%1,%2,%3}, {%4,%5,%6,%7}, {%8,%9}, {%0,%1,%2,%3};"
        : "+f"(c[0]), "+f"(c[1]), "+f"(c[2]), "+f"(c[3])
        : "r"(a[0]), "r"(a[1]), "r"(a[2]), "r"(a[3]), "r"(b[0]), "r"(b[1]));
}

__device__ __forceinline__ uint32_t pack_h2(float x, float y) {
    __half2 p;
    p.x = __float2half_rn(x);
    p.y = __float2half_rn(y);
    return *(uint32_t*)&p;
}

#define CP_ASYNC16(dst, src)                                                   \
    asm volatile("cp.async.cg.shared.global [%0], [%1], 16;"                   \
                 :: "r"(dst), "l"(src))
#define CP_COMMIT() asm volatile("cp.async.commit_group;" ::: "memory")
#define CP_WAIT0()  asm volatile("cp.async.wait_group 0;" ::: "memory")

// ===========================================================================
// One-time fp32 -> fp16 conversions
// ===========================================================================
__global__ __launch_bounds__(256)
void cvt_x(const float* __restrict__ src, __half* __restrict__ dst) {
    int i = (blockIdx.x * 256 + threadIdx.x) * 4;
    float4 v = *(const float4*)(src + i);
    *(uint2*)(dst + i) = make_uint2(pack_h2(v.x, v.y), pack_h2(v.z, v.w));
}

// all four weight matrices in one launch (blockIdx.y selects)
__global__ __launch_bounds__(256)
void cvt_w(const float* __restrict__ wq, const float* __restrict__ wk,
           const float* __restrict__ wv, const float* __restrict__ wo,
           __half* __restrict__ dq, __half* __restrict__ dk,
           __half* __restrict__ dv, __half* __restrict__ dwo) {
    int z = blockIdx.y;
    const float* src = (z == 0) ? wq : (z == 1) ? wk : (z == 2) ? wv : wo;
    __half* dst = (z == 0) ? dq : (z == 1) ? dk : (z == 2) ? dv : dwo;
    int i = (blockIdx.x * 256 + threadIdx.x) * 4;
    float4 v = *(const float4*)(src + i);
    *(uint2*)(dst + i) = make_uint2(pack_h2(v.x, v.y), pack_h2(v.z, v.w));
}

// ===========================================================================
// All-fp16 1-pass cp.async-pipelined GEMM-NT:  C = A * B^T
// 128x128 CTA tile, BK=32, 256 threads (8 warps 2x4), warp tile 64x32.
// MODE 1: out single fp16 (scaled)   (Q, K, V projections)
// MODE 2: out fp32                   (output projection)
// ===========================================================================
#define RS 40
#define SEG (128 * RS)
#define STAGE_ELEMS (2 * SEG)             // A | B
#define STAGE_BYTES (STAGE_ELEMS * 2)     // 20480
#define GEMM_SMEM (2 * STAGE_BYTES)       // 40960

template <int MODE>
__device__ __forceinline__
void gemm_body(const __half* __restrict__ Ax, const __half* __restrict__ Bw,
               float* __restrict__ C, __half* __restrict__ Ch,
               float scale, int M, int N, int Kd, __half* smem) {
    const uint32_t sb = smem_u32(smem);
    const int t    = threadIdx.x;
    const int lane = t & 31;
    const int wid  = t >> 5;
    const int wm   = (wid >> 2) * 64;
    const int wn   = (wid & 3) * 32;
    const int bm   = blockIdx.y * 128;
    const int bn   = blockIdx.x * 128;

    auto issue = [&](int c, int stage) {
        const int k0 = c * 32;
        uint32_t dbase = sb + stage * STAGE_BYTES;
#pragma unroll
        for (int i = 0; i < 4; i++) {
            int idx = t + i * 256;        // 0..1023
            int mtx = idx >> 9;           // 0=A 1=B
            int r   = (idx >> 2) & 127;
            int c16 = (idx & 3) * 8;
            const __half* src =
                (mtx == 0) ? Ax + (size_t)(bm + r) * Kd + k0 + c16
                           : Bw + (size_t)(bn + r) * Kd + k0 + c16;
            uint32_t dst = dbase + ((mtx * 128 + r) * RS + c16) * 2;
            CP_ASYNC16(dst, src);
        }
        CP_COMMIT();
    };

    float acc[4][4][4] = {};

    const int nchunks = Kd / 32;
    issue(0, 0);

    for (int c = 0; c < nchunks; c++) {
        const int stage = c & 1;
        CP_WAIT0();
        __syncthreads();
        if (c + 1 < nchunks) issue(c + 1, stage ^ 1);

        const uint32_t sstage = sb + stage * STAGE_BYTES;
        const uint32_t a_base =
            sstage + ((wm + (lane & 15)) * RS + (lane >> 4) * 8) * 2;
        const uint32_t b_base =
            sstage + SEG * 2 +
            ((wn + (lane & 15)) * RS + (lane >> 4) * 8) * 2;

#pragma unroll
        for (int ks = 0; ks < 2; ks++) {
            uint32_t ah[4][4];
#pragma unroll
            for (int mt = 0; mt < 4; mt++)
                ldm_x4(ah[mt], a_base + (mt * 16 * RS + ks * 16) * 2);
#pragma unroll
            for (int ntp = 0; ntp < 2; ntp++) {
                uint32_t fb[4];
                ldm_x4(fb, b_base + (ntp * 16 * RS + ks * 16) * 2);
                uint32_t be[2] = {fb[0], fb[2]};
                uint32_t bo[2] = {fb[1], fb[3]};
#pragma unroll
                for (int mt = 0; mt < 4; mt++) {
                    mma_f16(acc[mt][2 * ntp],     ah[mt], be);
                    mma_f16(acc[mt][2 * ntp + 1], ah[mt], bo);
                }
            }
        }
        __syncthreads();
    }

    const int r0 = bm + wm + (lane >> 2);
    const int c0 = bn + wn + (lane & 3) * 2;
#pragma unroll
    for (int mt = 0; mt < 4; mt++)
#pragma unroll
        for (int nt = 0; nt < 4; nt++) {
            size_t o0 = (size_t)(r0 + mt * 16) * N + c0 + nt * 8;
            size_t o1 = o0 + (size_t)8 * N;
            if (MODE == 2) {
                *(float2*)(C + o0) = make_float2(acc[mt][nt][0], acc[mt][nt][1]);
                *(float2*)(C + o1) = make_float2(acc[mt][nt][2], acc[mt][nt][3]);
            } else {
                *(uint32_t*)(Ch + o0) = pack_h2(acc[mt][nt][0] * scale,
                                                acc[mt][nt][1] * scale);
                *(uint32_t*)(Ch + o1) = pack_h2(acc[mt][nt][2] * scale,
                                                acc[mt][nt][3] * scale);
            }
        }
}

__global__ __launch_bounds__(256, 1)
void gemm_h(const __half* __restrict__ Ax, const __half* __restrict__ Bw,
            __half* __restrict__ Ch, float scale) {
    extern __shared__ __half smem[];
    gemm_body<1>(Ax, Bw, nullptr, Ch, scale, S_LEN, DIM, DIM, smem);
}
__global__ __launch_bounds__(256, 1)
void gemm_out(const __half* __restrict__ Ax, const __half* __restrict__ Bw,
              float* __restrict__ C) {
    extern __shared__ __half smem[];
    gemm_body<2>(Ax, Bw, C, nullptr, 1.0f, S_LEN, DIM, DIM, smem);
}

// ===========================================================================
// Tensor-core causal flash attention, all 1-pass fp16 mma.
// QK: Q (register-resident) x K.  PV: P single x V single.
// CTA = 128 q rows x 1 head; 512 threads = 8 row-groups x 2 key-halves.
// ===========================================================================
#define RS2 72
#define ATTN_SMEM (384 * RS2 * 2)   // 55296 bytes
#define MRG_STRIDE 68
#define MRG_GRP (16 * MRG_STRIDE + 32)

__global__ __launch_bounds__(512, 1)
void attn_mma(const __half* __restrict__ Q, const __half* __restrict__ K,
              const __half* __restrict__ V, __half* __restrict__ Z) {
    extern __shared__ __half sm[];
    const uint32_t sb = smem_u32(sm);
    const int qb   = (int)gridDim.x - 1 - (int)blockIdx.x;  // big tiles first
    const int h    = blockIdx.y;
    const int t    = threadIdx.x;
    const int lane = t & 31;
    const int w    = t >> 5;
    const int g    = w >> 1;      // row group 0..7
    const int hf   = w & 1;       // key half 0/1

    auto issue_kv = [&](int kb, int s) {
#pragma unroll
        for (int i = 0; i < 2; i++) {
            int idx = t + i * 512;
            int mtx = idx >> 9;           // 0=K 1=V
            int r   = (idx >> 3) & 63;
            int c8  = (idx & 7) * 8;
            const __half* src =
                (mtx ? V : K) + (size_t)(kb * 64 + r) * DIM + h * 64 + c8;
            uint32_t dst =
                sb + ((128 + s * 128 + mtx * 64 + r) * RS2 + c8) * 2;
            CP_ASYNC16(dst, src);
        }
    };

    // ---- prologue: Q + stage 0 K/V ----
    {
#pragma unroll
        for (int i = 0; i < 2; i++) {
            int idx = t + i * 512;
            int r   = (idx >> 3) & 127;
            int c8  = (idx & 7) * 8;
            const __half* src =
                Q + (size_t)(qb * 128 + r) * DIM + h * 64 + c8;
            uint32_t dst = sb + (r * RS2 + c8) * 2;
            CP_ASYNC16(dst, src);
        }
        issue_kv(0, 0);
        CP_COMMIT();
        CP_WAIT0();
    }
    __syncthreads();

    // ---- Q fragments: register-resident for the whole kb loop ----
    uint32_t qf[4][4];
    {
        const uint32_t q_base =
            sb + ((g * 16 + (lane & 15)) * RS2 + (lane >> 4) * 8) * 2;
#pragma unroll
        for (int ks = 0; ks < 4; ks++)
            ldm_x4(qf[ks], q_base + ks * 32);
    }

    float o[8][4] = {};
    float m0 = -1e30f, m1 = -1e30f, l0 = 0.f, l1 = 0.f;
    const int row0 = qb * 128 + g * 16 + (lane >> 2);

    const int nkb = 2 * qb + 2;
    for (int kb = 0; kb < nkb; kb++) {
        const int s = kb & 1;
        if (kb + 1 < nkb) { issue_kv(kb + 1, s ^ 1); CP_COMMIT(); }

        const bool active = (kb * 64 + hf * 32 <= qb * 128 + g * 16 + 15);
        if (active) {
            const int KB = 128 + s * 128;        // K rows
            const int VB = KB + 64;              // V rows

            // ---- S = Q K^T on this warp's 32 keys (fp16 1-pass) ----
            float c[4][4] = {};
#pragma unroll
            for (int ks = 0; ks < 4; ks++) {
#pragma unroll
                for (int ntp = 0; ntp < 2; ntp++) {
                    uint32_t fh[4];
                    uint32_t addr = sb +
                        ((KB + hf * 32 + ntp * 16 + (lane & 15)) * RS2 +
                         ks * 16 + (lane >> 4) * 8) * 2;
                    ldm_x4(fh, addr);
                    uint32_t beh[2] = {fh[0], fh[2]};
                    uint32_t boh[2] = {fh[1], fh[3]};
                    mma_f16(c[2 * ntp],     qf[ks], beh);
                    mma_f16(c[2 * ntp + 1], qf[ks], boh);
                }
            }

            // ---- causal mask ----
            if (kb * 64 + hf * 32 + 31 > row0) {
                const int colbase = kb * 64 + hf * 32 + (lane & 3) * 2;
#pragma unroll
                for (int nt = 0; nt < 4; nt++) {
                    int cc = colbase + nt * 8;
                    if (cc     > row0)     c[nt][0] = -1e30f;
                    if (cc + 1 > row0)     c[nt][1] = -1e30f;
                    if (cc     > row0 + 8) c[nt][2] = -1e30f;
                    if (cc + 1 > row0 + 8) c[nt][3] = -1e30f;
                }
            }

            // ---- online softmax (log2 domain) ----
            float mx0 = -1e30f, mx1 = -1e30f;
#pragma unroll
            for (int nt = 0; nt < 4; nt++) {
                mx0 = fmaxf(mx0, fmaxf(c[nt][0], c[nt][1]));
                mx1 = fmaxf(mx1, fmaxf(c[nt][2], c[nt][3]));
            }
            mx0 = fmaxf(mx0, __shfl_xor_sync(0xffffffffu, mx0, 1));
            mx0 = fmaxf(mx0, __shfl_xor_sync(0xffffffffu, mx0, 2));
            mx1 = fmaxf(mx1, __shfl_xor_sync(0xffffffffu, mx1, 1));
            mx1 = fmaxf(mx1, __shfl_xor_sync(0xffffffffu, mx1, 2));
            float M0 = fmaxf(m0, mx0);
            float M1 = fmaxf(m1, mx1);
            float sc0 = exp2f(m0 - M0);
            float sc1 = exp2f(m1 - M1);
            m0 = M0; m1 = M1;
            float s0 = 0.f, s1 = 0.f;
#pragma unroll
            for (int nt = 0; nt < 4; nt++) {
                c[nt][0] = exp2f(c[nt][0] - M0);
                c[nt][1] = exp2f(c[nt][1] - M0);
                c[nt][2] = exp2f(c[nt][2] - M1);
                c[nt][3] = exp2f(c[nt][3] - M1);
                s0 += c[nt][0] + c[nt][1];
                s1 += c[nt][2] + c[nt][3];
            }
            s0 += __shfl_xor_sync(0xffffffffu, s0, 1);
            s0 += __shfl_xor_sync(0xffffffffu, s0, 2);
            s1 += __shfl_xor_sync(0xffffffffu, s1, 1);
            s1 += __shfl_xor_sync(0xffffffffu, s1, 2);
            l0 = l0 * sc0 + s0;
            l1 = l1 * sc1 + s1;
#pragma unroll
            for (int nt = 0; nt < 8; nt++) {
                o[nt][0] *= sc0; o[nt][1] *= sc0;
                o[nt][2] *= sc1; o[nt][3] *= sc1;
            }

            // ---- O += P V (fp16 1-pass: P single x V single) ----
#pragma unroll
            for (int ks = 0; ks < 2; ks++) {
                uint32_t ph[4];
                ph[0] = pack_h2(c[2 * ks][0],     c[2 * ks][1]);
                ph[1] = pack_h2(c[2 * ks][2],     c[2 * ks][3]);
                ph[2] = pack_h2(c[2 * ks + 1][0], c[2 * ks + 1][1]);
                ph[3] = pack_h2(c[2 * ks + 1][2], c[2 * ks + 1][3]);
#pragma unroll
                for (int ntp = 0; ntp < 4; ntp++) {
                    uint32_t fh[4];
                    uint32_t addr = sb +
                        ((VB + hf * 32 + ks * 16 + (lane & 15)) * RS2 +
                         ntp * 16 + (lane >> 4) * 8) * 2;
                    ldm_x4t(fh, addr);
                    uint32_t veh[2] = {fh[0], fh[1]};
                    uint32_t voh[2] = {fh[2], fh[3]};
                    mma_f16(o[2 * ntp],     ph, veh);
                    mma_f16(o[2 * ntp + 1], ph, voh);
                }
            }
        }
        if (kb + 1 < nkb) CP_WAIT0();
        __syncthreads();
    }

    // ---- merge warp pairs via smem (hf=1 publishes, hf=0 merges+stores) ----
    float* smf = (float*)sm;
    const int r4 = lane >> 2;
    const int c2 = (lane & 3) * 2;
    if (hf == 1) {
        float* gbuf = smf + g * MRG_GRP;
#pragma unroll
        for (int nt = 0; nt < 8; nt++) {
            float* p0 = gbuf + r4 * MRG_STRIDE + c2 + nt * 8;
            p0[0] = o[nt][0];
            p0[1] = o[nt][1];
            float* p1 = gbuf + (r4 + 8) * MRG_STRIDE + c2 + nt * 8;
            p1[0] = o[nt][2];
            p1[1] = o[nt][3];
        }
        if ((lane & 3) == 0) {
            gbuf[16 * MRG_STRIDE + r4]      = m0;
            gbuf[16 * MRG_STRIDE + 8 + r4]  = m1;
            gbuf[16 * MRG_STRIDE + 16 + r4] = l0;
            gbuf[16 * MRG_STRIDE + 24 + r4] = l1;
        }
    }
    __syncthreads();
    if (hf == 0) {
        float* gbuf = smf + g * MRG_GRP;
        float mb0 = gbuf[16 * MRG_STRIDE + r4];
        float mb1 = gbuf[16 * MRG_STRIDE + 8 + r4];
        float lb0 = gbuf[16 * MRG_STRIDE + 16 + r4];
        float lb1 = gbuf[16 * MRG_STRIDE + 24 + r4];
        float M0 = fmaxf(m0, mb0);
        float M1 = fmaxf(m1, mb1);
        float ea0 = exp2f(m0 - M0), eb0 = exp2f(mb0 - M0);
        float ea1 = exp2f(m1 - M1), eb1 = exp2f(mb1 - M1);
        float inv0 = 1.0f / (l0 * ea0 + lb0 * eb0);
        float inv1 = 1.0f / (l1 * ea1 + lb1 * eb1);
        size_t zoff0 = (size_t)row0 * DIM + h * HD + c2;
        size_t zoff1 = zoff0 + (size_t)8 * DIM;
#pragma unroll
        for (int nt = 0; nt < 8; nt++) {
            float* p0 = gbuf + r4 * MRG_STRIDE + c2 + nt * 8;
            float* p1 = gbuf + (r4 + 8) * MRG_STRIDE + c2 + nt * 8;
            float a0 = (o[nt][0] * ea0 + p0[0] * eb0) * inv0;
            float a1 = (o[nt][1] * ea0 + p0[1] * eb0) * inv0;
            float b0 = (o[nt][2] * ea1 + p1[0] * eb1) * inv1;
            float b1 = (o[nt][3] * ea1 + p1[1] * eb1) * inv1;
            *(uint32_t*)(Z + zoff0 + nt * 8) = pack_h2(a0, a1);
            *(uint32_t*)(Z + zoff1 + nt * 8) = pack_h2(b0, b1);
        }
    }
}

// ===========================================================================
extern "C" void kernel_launch(void* const* d_in, const int* in_sizes, int n_in,
                              void* d_out, int out_size) {
    const float* x  = (const float*)d_in[0];
    const float* Wq = (const float*)d_in[1];
    const float* Wk = (const float*)d_in[2];
    const float* Wv = (const float*)d_in[3];
    const float* Wo = (const float*)d_in[4];
    float* out = (float*)d_out;

    __half *dx, *dwq, *dwk, *dwv, *dwo, *dQ, *dK, *dV, *dZ;
    cudaGetSymbolAddress((void**)&dx, g_x);
    cudaGetSymbolAddress((void**)&dwq, g_wq);
    cudaGetSymbolAddress((void**)&dwk, g_wk);
    cudaGetSymbolAddress((void**)&dwv, g_wv);
    cudaGetSymbolAddress((void**)&dwo, g_wo);
    cudaGetSymbolAddress((void**)&dQ, g_Q);
    cudaGetSymbolAddress((void**)&dK, g_K);
    cudaGetSymbolAddress((void**)&dV, g_V);
    cudaGetSymbolAddress((void**)&dZ, g_Z);

    cudaFuncSetAttribute(gemm_h,
                         cudaFuncAttributeMaxDynamicSharedMemorySize, GEMM_SMEM);
    cudaFuncSetAttribute(gemm_out,
                         cudaFuncAttributeMaxDynamicSharedMemorySize, GEMM_SMEM);
    cudaFuncSetAttribute(attn_mma,
                         cudaFuncAttributeMaxDynamicSharedMemorySize, ATTN_SMEM);

    // one-time fp16 conversions
    cvt_x<<<(S_LEN * DIM) / 1024, 256>>>(x, dx);
    cvt_w<<<dim3((DIM * DIM) / 1024, 4), 256>>>(Wq, Wk, Wv, Wo,
                                                dwq, dwk, dwv, dwo);

    dim3 gproj(DIM / 128, S_LEN / 128);   // (8, 32)
    gemm_h<<<gproj, 256, GEMM_SMEM>>>(dx, dwq, dQ, QSCALE);
    gemm_h<<<gproj, 256, GEMM_SMEM>>>(dx, dwk, dK, 1.0f);
    gemm_h<<<gproj, 256, GEMM_SMEM>>>(dx, dwv, dV, 1.0f);

    attn_mma<<<dim3(S_LEN / 128, NH), 512, ATTN_SMEM>>>(dQ, dK, dV, dZ);

    gemm_out<<<gproj, 256, GEMM_SMEM>>>(dZ, dwo, out);
}